// round 3
// baseline (speedup 1.0000x reference)
#include <cuda_runtime.h>

#define CC   2
#define HH   200
#define WW   200
#define NN   200
#define HWN  (HH*WW*NN)
#define N8   (NN/8)                     // 25 groups of 8 n per (h,w)
#define TOTAL_THREADS (HH*WW*N8)        // 1,000,000

// Factorized per-axis cell tables (int8):
//   g_cx[w*NN + n] = cx in {0,1}, or -1 if x outside [x1,x2]
//   g_cy[h*NN + n] = cy in {0,1}, or -1 if y outside [y1,y2]
__device__ signed char g_cx[WW * NN];
__device__ signed char g_cy[HH * NN];

__global__ void prep_kernel(const float* __restrict__ rois) {
    int idx = blockIdx.x * blockDim.x + threadIdx.x;   // [0, 2*200*200)
    if (idx >= 2 * WW * NN) return;

    int axis = idx / (WW * NN);     // 0 = x, 1 = y
    int rem  = idx % (WW * NN);
    int p    = rem / NN;            // pixel coord (w or h)
    int n    = rem % NN;

    float lo = rois[4 * n + (axis ? 1 : 0)];   // x1 or y1
    float hi = rois[4 * n + (axis ? 3 : 2)];   // x2 or y2
    float cl = fmaxf(hi - lo, 1.0f);
    // double-precision reciprocal so (p-lo)*s tracks fp32 CC*(p-lo)/cl to ~1 ulp
    float s  = (float)((double)CC / (double)cl);

    float pf = (float)p;
    signed char v = -1;
    if (pf >= lo && pf <= hi) {
        int c = (int)floorf((pf - lo) * s);
        c = min(max(c, 0), CC - 1);
        v = (signed char)c;
    }
    if (axis == 0) g_cx[p * NN + n] = v;
    else           g_cy[p * NN + n] = v;
}

__global__ void __launch_bounds__(256)
crop_split_kernel(const float* __restrict__ data, float* __restrict__ out) {
    int idx = blockIdx.x * 256 + threadIdx.x;
    if (idx >= TOTAL_THREADS) return;

    int n8 = idx % N8;          // group of 8 consecutive n
    int hw = idx / N8;          // h*WW + w
    int w  = hw % WW;
    int h  = hw / WW;

    int base = hw * NN + n8 * 8;     // 32B-aligned output segment

    // 8B of metadata per table (offsets are 8B-aligned: 200 % 8 == 0)
    uint2 cxu = *reinterpret_cast<const uint2*>(g_cx + w * NN + n8 * 8);
    uint2 cyu = *reinterpret_cast<const uint2*>(g_cy + h * NN + n8 * 8);

    float v[8];
    #pragma unroll
    for (int i = 0; i < 8; i++) {
        unsigned xw = (i < 4) ? cxu.x : cxu.y;
        unsigned yw = (i < 4) ? cyu.x : cyu.y;
        int cx = (int)(signed char)(xw >> (8 * (i & 3)));
        int cy = (int)(signed char)(yw >> (8 * (i & 3)));
        float val = 0.0f;
        if ((cx | cy) >= 0) {
            int cell = cy * CC + cx;
            // streaming load: gather sectors have zero reuse, keep L1 for tables
            val = __ldcs(data + (size_t)cell * HWN + base + i);
        }
        v[i] = val;
    }

    float4 o0 = make_float4(v[0], v[1], v[2], v[3]);
    float4 o1 = make_float4(v[4], v[5], v[6], v[7]);
    __stcs(reinterpret_cast<float4*>(out + base),     o0);
    __stcs(reinterpret_cast<float4*>(out + base) + 1, o1);
}

extern "C" void kernel_launch(void* const* d_in, const int* in_sizes, int n_in,
                              void* d_out, int out_size) {
    const float* data = (const float*)d_in[0];   // (4, H, W, N) fp32
    const float* rois = (const float*)d_in[1];   // (N, 4) fp32
    float* out = (float*)d_out;                  // (H, W, N) fp32

    int prep_elems = 2 * WW * NN;                // 80000
    prep_kernel<<<(prep_elems + 255) / 256, 256>>>(rois);

    int blocks = (TOTAL_THREADS + 255) / 256;    // 3907
    crop_split_kernel<<<blocks, 256>>>(data, out);
}